// round 15
// baseline (speedup 1.0000x reference)
#include <cuda_runtime.h>

// Problem constants: B=4, K=32, H=W=128
#define KK  32
#define LLn 128
#define LM1 127
#define RR  128
#define RT  8
#define NB  4
#define NN  2097152  // B*K*H*W

// Scratch (static device arrays -- no allocation)
__device__ float g_hpT[4 * 32 * 32 * 127 * 128];  // horizontal pairwise transposed [b,i,j,l(=w),h]
__device__ float g_huT[NN];                       // horizontal unary transposed [b,k,w,h]
__device__ float g_Lh[NN];                        // horizontal forward scan (T layout)
__device__ float g_Rh[NN];                        // horizontal backward scan (T layout)
__device__ float g_Lv[NN];                        // vertical forward scan (std layout)
__device__ float g_Rv[NN];                        // vertical backward scan (std layout)

// ---------------------------------------------------------------------------
// Tiled transpose of the inner 2D [rows, cols] -> [cols, rows] per slab.
// which==0 -> g_hpT, which==1 -> g_huT.
// ---------------------------------------------------------------------------
__global__ void transpose_k(const float* __restrict__ in, int which, int rows, int cols)
{
    float* __restrict__ out = (which == 0) ? g_hpT : g_huT;
    __shared__ float t[32][33];
    const int slab = blockIdx.z;
    const size_t base = (size_t)slab * rows * cols;
    const int c0 = blockIdx.x * 32, r0 = blockIdx.y * 32;

    #pragma unroll
    for (int yy = 0; yy < 32; yy += 8) {
        int r = r0 + threadIdx.y + yy;
        int c = c0 + threadIdx.x;
        if (r < rows && c < cols)
            t[threadIdx.y + yy][threadIdx.x] = in[base + (size_t)r * cols + c];
    }
    __syncthreads();
    #pragma unroll
    for (int yy = 0; yy < 32; yy += 8) {
        int c = c0 + threadIdx.y + yy;
        int r = r0 + threadIdx.x;
        if (r < rows && c < cols)
            out[base + (size_t)c * rows + r] = t[threadIdx.x][threadIdx.y + yy];
    }
}

// ---------------------------------------------------------------------------
// Fused scan kernel: blockIdx.z selects {0: h-fwd, 1: h-bwd, 2: v-fwd, 3: v-bwd}.
// Layouts (after transpose for horizontal):
//   pairwise p[b, a, c, l, r]  (a = outer state, c = inner state, l = step, r = lane)
//   unary    u[b, k, l, r]
// Forward : new[j] = u[l][j] + g*lse_i( p[b,i,j,l-1,r] + carry[i] )
// Backward: new[i] = u[l][i] + g*lse_j( p[b,i,j,l,  r] + carry[j] )
// Thread (rl, jo): rl = lane within r-tile (coalescing), jo = output state.
// Carry vector lives in smem, 32-wide reduction over inner state in registers.
// ---------------------------------------------------------------------------
__global__ void __launch_bounds__(256, 2) scan_all(
    const float* __restrict__ vp, const float* __restrict__ vu,
    const float* __restrict__ gamma_ptr)
{
    const int mode  = blockIdx.z;
    const bool horiz = mode < 2;
    const bool fwd   = (mode & 1) == 0;
    const float* __restrict__ p = horiz ? g_hpT : vp;
    const float* __restrict__ u = horiz ? g_huT : vu;
    float* __restrict__ out = (mode == 0) ? g_Lh : (mode == 1) ? g_Rh
                            : (mode == 2) ? g_Lv : g_Rv;

    const float g   = gamma_ptr[0];
    const float kk  = 1.4426950408889634f / g;    // 1/(g*ln2)
    const float gl2 = g * 0.69314718055994531f;   // g*ln2

    const int rl = threadIdx.x;                   // 0..7
    const int jo = threadIdx.y;                   // 0..31 (output state)
    const int r  = blockIdx.x * RT + rl;
    const int b  = blockIdx.y;

    __shared__ float csh[KK][RT];

    const size_t uBase = ((size_t)(b * KK + jo)) * LLn * RR + r;
    const int l0 = fwd ? 0 : (LLn - 1);
    float cv = u[uBase + (size_t)l0 * RR];
    csh[jo][rl] = cv;
    out[uBase + (size_t)l0 * RR] = cv;
    __syncthreads();

    // p index: ((b*K + a)*K + c)*LM1*R + pl*R + r
    // fwd: a = inner i (stride K*LM1*R), c = jo.   bwd: a = jo, c = inner j (stride LM1*R).
    const size_t strideInner = fwd ? (size_t)KK * LM1 * RR : (size_t)LM1 * RR;
    const size_t pBase = ((size_t)b * KK * KK + (size_t)jo * (fwd ? 1 : KK)) * (size_t)LM1 * RR + r;

    for (int s = 1; s < LLn; ++s) {
        const int l  = fwd ? s : (LLn - 1 - s);
        const int pl = fwd ? (s - 1) : l;
        const float* __restrict__ pp = p + pBase + (size_t)pl * RR;

        float v[KK];
        #pragma unroll
        for (int i = 0; i < KK; ++i)
            v[i] = pp[(size_t)i * strideInner] + csh[i][rl];

        float m = v[0];
        #pragma unroll
        for (int i = 1; i < KK; ++i) m = fmaxf(m, v[i]);

        const float mk = m * kk;
        float ssum = 0.0f;
        #pragma unroll
        for (int i = 0; i < KK; ++i) {
            float e;
            asm("ex2.approx.ftz.f32 %0, %1;" : "=f"(e) : "f"(fmaf(v[i], kk, -mk)));
            ssum += e;
        }
        float lg;
        asm("lg2.approx.f32 %0, %1;" : "=f"(lg) : "f"(ssum));

        const float nv = u[uBase + (size_t)l * RR] + m + lg * gl2;

        __syncthreads();               // all reads of old carry done
        csh[jo][rl] = nv;
        out[uBase + (size_t)l * RR] = nv;
        __syncthreads();               // new carry visible
    }
}

// ---------------------------------------------------------------------------
// Combine: hm = transpose(Lh + Rh - huT), vm = Lv + Rv - vu,
//          d = hm - vm, hn = hu - d/(2W), vn = vu + d/(2H).
// Out sections: [0]=hn, [1]=vn, [2]=hm, [3]=vm.  H=W=128 -> 1/256 factor.
// ---------------------------------------------------------------------------
__global__ void combine_k(const float* __restrict__ hu, const float* __restrict__ vu,
                          float* __restrict__ out)
{
    __shared__ float t[32][33];
    const int bk = blockIdx.z;
    const size_t base = (size_t)bk * 128 * 128;
    const int w0 = blockIdx.x * 32, h0 = blockIdx.y * 32;

    // Load T-layout tile (indexed [w][h]) with h contiguous.
    #pragma unroll
    for (int yy = 0; yy < 32; yy += 8) {
        int w = w0 + threadIdx.y + yy;
        int h = h0 + threadIdx.x;
        size_t i = base + (size_t)w * 128 + h;
        t[threadIdx.y + yy][threadIdx.x] = g_Lh[i] + g_Rh[i] - g_huT[i];
    }
    __syncthreads();
    #pragma unroll
    for (int yy = 0; yy < 32; yy += 8) {
        int h = h0 + threadIdx.y + yy;
        int w = w0 + threadIdx.x;
        size_t i = base + (size_t)h * 128 + w;
        float hm = t[threadIdx.x][threadIdx.y + yy];
        float vuv = vu[i];
        float vm = g_Lv[i] + g_Rv[i] - vuv;
        float d  = hm - vm;
        out[i]            = hu[i] - d * (1.0f / 256.0f);
        out[NN + i]       = vuv + d * (1.0f / 256.0f);
        out[2 * NN + i]   = hm;
        out[3 * NN + i]   = vm;
    }
}

// ---------------------------------------------------------------------------
extern "C" void kernel_launch(void* const* d_in, const int* in_sizes, int n_in,
                              void* d_out, int out_size)
{
    const float* hu    = (const float*)d_in[0];  // horizontal_unary  [B,K,H,W]
    const float* vu    = (const float*)d_in[1];  // vertical_unary    [B,K,H,W]
    const float* hp    = (const float*)d_in[2];  // horizontal_pairwise [B,K,K,H,W-1]
    const float* vp    = (const float*)d_in[3];  // vertical_pairwise   [B,K,K,H-1,W]
    const float* gamma = (const float*)d_in[4];  // [1]
    float* out = (float*)d_out;

    // 1) Transpose horizontal pairwise [h, l] -> [l, h] per (b,i,j) slab,
    //    and horizontal unary [h, w] -> [w, h] per (b,k) slab.
    transpose_k<<<dim3(4, 4, NB * KK * KK), dim3(32, 8)>>>(hp, 0, 128, 127);
    transpose_k<<<dim3(4, 4, NB * KK),      dim3(32, 8)>>>(hu, 1, 128, 128);

    // 2) All four scans in one launch (z = mode).
    scan_all<<<dim3(RR / RT, NB, 4), dim3(RT, KK)>>>(vp, vu, gamma);

    // 3) Combine + transpose-back + write all 4 output sections.
    combine_k<<<dim3(4, 4, NB * KK), dim3(32, 8)>>>(hu, vu, out);
}

// round 16
// speedup vs baseline: 1.1279x; 1.1279x over previous
#include <cuda_runtime.h>
#include <cuda_fp16.h>

// Problem constants: B=4, K=32, H=W=128
#define KK  32
#define LLn 128
#define LM1 127
#define RR  128
#define RT  8
#define NB  4
#define NN  2097152  // B*K*H*W

// Scratch (static device arrays -- no allocation)
// g_hpF: horizontal pairwise, transposed (l=w, r=h innermost), fp16, packed as
// half2 over source-state pairs: plane(b,i2,j) holds half2(p[2i2,j], p[2i2+1,j]).
__device__ __half2 g_hpF[(size_t)NB * 16 * KK * LM1 * RR];
__device__ float g_huT[NN];                       // horizontal unary transposed [b,k,w,h]
__device__ float g_Lh[NN];                        // horizontal forward scan (T layout)
__device__ float g_Rh[NN];                        // horizontal backward scan (T layout)
__device__ float g_Lv[NN];                        // vertical forward scan (std layout)
__device__ float g_Rv[NN];                        // vertical backward scan (std layout)

// ---------------------------------------------------------------------------
// Pack + transpose horizontal pairwise: reads slabs (b,2*i2,j) and (b,2*i2+1,j)
// ([h][w] tiles), writes transposed [l=w][r=h] half2 pairs. Full-sector reads
// and writes; each input element touched exactly once.
// ---------------------------------------------------------------------------
__global__ void pack_hp(const float* __restrict__ hp)
{
    __shared__ float t0[32][33], t1[32][33];
    const int z  = blockIdx.z;             // b*512 + i2*32 + j
    const int j  = z & 31;
    const int i2 = (z >> 5) & 15;
    const int b  = z >> 9;
    // hp index: (((b*32 + i)*32 + j)*128 + h)*127 + w
    const size_t in0 = ((size_t)(b * 1024 + i2 * 64 + j)) * (size_t)(128 * 127);
    const size_t in1 = in0 + (size_t)32 * 128 * 127;
    const int c0 = blockIdx.x * 32, r0 = blockIdx.y * 32;   // c=w(127), r=h(128)

    #pragma unroll
    for (int yy = 0; yy < 32; yy += 8) {
        int h = r0 + threadIdx.y + yy;
        int w = c0 + threadIdx.x;
        if (w < 127) {
            t0[threadIdx.y + yy][threadIdx.x] = hp[in0 + (size_t)h * 127 + w];
            t1[threadIdx.y + yy][threadIdx.x] = hp[in1 + (size_t)h * 127 + w];
        }
    }
    __syncthreads();
    #pragma unroll
    for (int yy = 0; yy < 32; yy += 8) {
        int l = c0 + threadIdx.y + yy;     // w -> step
        int r = r0 + threadIdx.x;          // h -> lane
        if (l < 127)
            g_hpF[((size_t)z * 127 + l) * 128 + r] =
                __floats2half2_rn(t0[threadIdx.x][threadIdx.y + yy],
                                  t1[threadIdx.x][threadIdx.y + yy]);
    }
}

// ---------------------------------------------------------------------------
// Transpose horizontal unary [b,k,h,w] -> g_huT [b,k,w,h].
// ---------------------------------------------------------------------------
__global__ void transpose_hu(const float* __restrict__ in)
{
    __shared__ float t[32][33];
    const size_t base = (size_t)blockIdx.z * 128 * 128;
    const int c0 = blockIdx.x * 32, r0 = blockIdx.y * 32;

    #pragma unroll
    for (int yy = 0; yy < 32; yy += 8) {
        int r = r0 + threadIdx.y + yy;
        int c = c0 + threadIdx.x;
        t[threadIdx.y + yy][threadIdx.x] = in[base + (size_t)r * 128 + c];
    }
    __syncthreads();
    #pragma unroll
    for (int yy = 0; yy < 32; yy += 8) {
        int c = c0 + threadIdx.y + yy;
        int r = r0 + threadIdx.x;
        g_huT[base + (size_t)c * 128 + r] = t[threadIdx.x][threadIdx.y + yy];
    }
}

// ---------------------------------------------------------------------------
// 32-wide smoothed-max (g * logsumexp) over a register array.
// ---------------------------------------------------------------------------
__device__ __forceinline__ float lse32(const float* v, float kkc, float gl2)
{
    float m = v[0];
    #pragma unroll
    for (int i = 1; i < KK; ++i) m = fmaxf(m, v[i]);
    const float mk = m * kkc;
    float ssum = 0.0f;
    #pragma unroll
    for (int i = 0; i < KK; ++i) {
        float e;
        asm("ex2.approx.ftz.f32 %0, %1;" : "=f"(e) : "f"(fmaf(v[i], kkc, -mk)));
        ssum += e;
    }
    float lg;
    asm("lg2.approx.f32 %0, %1;" : "=f"(lg) : "f"(ssum));
    return m + lg * gl2;
}

// ---------------------------------------------------------------------------
// Fused scan kernel: blockIdx.z selects {0: h-fwd, 1: h-bwd, 2: v-fwd, 3: v-bwd}.
// Horizontal reads the fp16 pair-packed g_hpF; vertical reads vp f32 directly.
// Thread (rl, jo): rl = lane within r-tile (coalescing), jo = output state.
// Carry vector lives in smem, 32-wide reduction over inner state in registers.
// ---------------------------------------------------------------------------
__global__ void __launch_bounds__(256, 2) scan_all(
    const float* __restrict__ vp, const float* __restrict__ vu,
    const float* __restrict__ gamma_ptr)
{
    const int mode   = blockIdx.z;
    const bool horiz = mode < 2;
    const bool fwd   = (mode & 1) == 0;
    const float* __restrict__ u = horiz ? g_huT : vu;
    float* __restrict__ out = (mode == 0) ? g_Lh : (mode == 1) ? g_Rh
                            : (mode == 2) ? g_Lv : g_Rv;

    const float g   = gamma_ptr[0];
    const float kkc = 1.4426950408889634f / g;    // 1/(g*ln2)
    const float gl2 = g * 0.69314718055994531f;   // g*ln2

    const int rl = threadIdx.x;                   // 0..7
    const int jo = threadIdx.y;                   // 0..31 (output state)
    const int r  = blockIdx.x * RT + rl;
    const int b  = blockIdx.y;

    __shared__ float csh[KK][RT];

    const size_t uBase = ((size_t)(b * KK + jo)) * LLn * RR + r;
    const int l0 = fwd ? 0 : (LLn - 1);
    float cv = u[uBase + (size_t)l0 * RR];
    csh[jo][rl] = cv;
    out[uBase + (size_t)l0 * RR] = cv;
    __syncthreads();

    if (horiz) {
        if (fwd) {
            // new[j] = u[l][j] + g*lse_i( p[i,j,l-1] + c[i] ); inner i as half2 pairs.
            const __half2* __restrict__ pf = g_hpF;
            const size_t pBase = ((size_t)(b * 512 + jo) * 127) * 128 + r;
            for (int s = 1; s < LLn; ++s) {
                const int l = s, pl = s - 1;
                const __half2* __restrict__ pp = pf + pBase + (size_t)pl * 128;
                float v[KK];
                #pragma unroll
                for (int i2 = 0; i2 < 16; ++i2) {
                    float2 f = __half22float2(pp[(size_t)i2 * (32 * 127 * 128)]);
                    v[2 * i2]     = f.x + csh[2 * i2][rl];
                    v[2 * i2 + 1] = f.y + csh[2 * i2 + 1][rl];
                }
                const float nv = u[uBase + (size_t)l * RR] + lse32(v, kkc, gl2);
                __syncthreads();
                csh[jo][rl] = nv;
                out[uBase + (size_t)l * RR] = nv;
                __syncthreads();
            }
        } else {
            // new[i] = u[l][i] + g*lse_j( p[i,j,l] + c[j] ); i = jo, read own half.
            // Threads jo=2k and jo=2k+1 share the same half2 stream -> full sectors.
            const __half* __restrict__ ph = (const __half*)g_hpF;
            const size_t pBase =
                (((size_t)(b * 16 + (jo >> 1)) * 32) * 127) * 256 + 2 * r + (jo & 1);
            for (int s = 1; s < LLn; ++s) {
                const int l = LLn - 1 - s, pl = l;
                const __half* __restrict__ pp = ph + pBase + (size_t)pl * 256;
                float v[KK];
                #pragma unroll
                for (int j = 0; j < KK; ++j)
                    v[j] = __half2float(pp[(size_t)j * (127 * 256)]) + csh[j][rl];
                const float nv = u[uBase + (size_t)l * RR] + lse32(v, kkc, gl2);
                __syncthreads();
                csh[jo][rl] = nv;
                out[uBase + (size_t)l * RR] = nv;
                __syncthreads();
            }
        }
    } else {
        // Vertical: read vp f32 directly (already scan-friendly layout).
        const size_t strideInner = fwd ? (size_t)KK * LM1 * RR : (size_t)LM1 * RR;
        const size_t pBase = ((size_t)b * KK * KK + (size_t)jo * (fwd ? 1 : KK))
                             * (size_t)LM1 * RR + r;
        for (int s = 1; s < LLn; ++s) {
            const int l  = fwd ? s : (LLn - 1 - s);
            const int pl = fwd ? (s - 1) : l;
            const float* __restrict__ pp = vp + pBase + (size_t)pl * RR;
            float v[KK];
            #pragma unroll
            for (int i = 0; i < KK; ++i)
                v[i] = pp[(size_t)i * strideInner] + csh[i][rl];
            const float nv = u[uBase + (size_t)l * RR] + lse32(v, kkc, gl2);
            __syncthreads();
            csh[jo][rl] = nv;
            out[uBase + (size_t)l * RR] = nv;
            __syncthreads();
        }
    }
}

// ---------------------------------------------------------------------------
// Combine: hm = transpose(Lh + Rh - huT), vm = Lv + Rv - vu,
//          d = hm - vm, hn = hu - d/(2W), vn = vu + d/(2H).
// Out sections: [0]=hn, [1]=vn, [2]=hm, [3]=vm.  H=W=128 -> 1/256 factor.
// ---------------------------------------------------------------------------
__global__ void combine_k(const float* __restrict__ hu, const float* __restrict__ vu,
                          float* __restrict__ out)
{
    __shared__ float t[32][33];
    const int bk = blockIdx.z;
    const size_t base = (size_t)bk * 128 * 128;
    const int w0 = blockIdx.x * 32, h0 = blockIdx.y * 32;

    #pragma unroll
    for (int yy = 0; yy < 32; yy += 8) {
        int w = w0 + threadIdx.y + yy;
        int h = h0 + threadIdx.x;
        size_t i = base + (size_t)w * 128 + h;
        t[threadIdx.y + yy][threadIdx.x] = g_Lh[i] + g_Rh[i] - g_huT[i];
    }
    __syncthreads();
    #pragma unroll
    for (int yy = 0; yy < 32; yy += 8) {
        int h = h0 + threadIdx.y + yy;
        int w = w0 + threadIdx.x;
        size_t i = base + (size_t)h * 128 + w;
        float hm  = t[threadIdx.x][threadIdx.y + yy];
        float vuv = vu[i];
        float vm  = g_Lv[i] + g_Rv[i] - vuv;
        float d   = hm - vm;
        out[i]          = hu[i] - d * (1.0f / 256.0f);
        out[NN + i]     = vuv + d * (1.0f / 256.0f);
        out[2 * NN + i] = hm;
        out[3 * NN + i] = vm;
    }
}

// ---------------------------------------------------------------------------
extern "C" void kernel_launch(void* const* d_in, const int* in_sizes, int n_in,
                              void* d_out, int out_size)
{
    const float* hu    = (const float*)d_in[0];  // horizontal_unary  [B,K,H,W]
    const float* vu    = (const float*)d_in[1];  // vertical_unary    [B,K,H,W]
    const float* hp    = (const float*)d_in[2];  // horizontal_pairwise [B,K,K,H,W-1]
    const float* vp    = (const float*)d_in[3];  // vertical_pairwise   [B,K,K,H-1,W]
    const float* gamma = (const float*)d_in[4];  // [1]
    float* out = (float*)d_out;

    // 1) Pack+transpose horizontal pairwise to fp16 half2 pairs; transpose unary.
    pack_hp<<<dim3(4, 4, NB * 16 * KK), dim3(32, 8)>>>(hp);
    transpose_hu<<<dim3(4, 4, NB * KK), dim3(32, 8)>>>(hu);

    // 2) All four scans in one launch (z = mode).
    scan_all<<<dim3(RR / RT, NB, 4), dim3(RT, KK)>>>(vp, vu, gamma);

    // 3) Combine + transpose-back + write all 4 output sections.
    combine_k<<<dim3(4, 4, NB * KK), dim3(32, 8)>>>(hu, vu, out);
}